// round 17
// baseline (speedup 1.0000x reference)
#include <cuda_runtime.h>
#include <cuda_fp16.h>
#include <math.h>

#define NN    50000
#define NE    800000
#define INF_  32
#define H     64
#define HV    16      // H/4 (float4 lanes per row)
#define EDIM  4
#define NL    3
#define NG    512
#define NOUT  2
#define NPAD  50048   // 391 * 128
#define BN_EPS 1e-5f
#define PN_EPS 1e-5f
#define EPB   128     // edges per block in edge_kernel (4 per 8-thread group)
#define KP    72      // padded halves per row in mma smem tiles
#define MROWS 128     // rows per mlp block

// ---------------- persistent device scratch (zero-initialized at load) -----
__device__ float d_h[NPAD * H];
__device__ __align__(16) __half d_h16[NPAD * H];    // fp16 shadow for gathers
__device__ __align__(16) __half d_agg16[NPAD * H];  // fp16 aggregation buffer
__device__ float d_gsum[NG * H];
__device__ float d_gss[NG];
__device__ float d_gcnt[NG];
__device__ float d_mean[NG * H];
__device__ float d_invd[NG];
__device__ float d_pool[NG * H];

__device__ __forceinline__ void red_add2(float2* a, float v0, float v1) {
    asm volatile("red.global.add.v2.f32 [%0], {%1,%2};"
                 :: "l"(a), "f"(v0), "f"(v1) : "memory");
}
// 16-byte fp16x2 vector reduction (8 halves)
__device__ __forceinline__ void red_addh8(uint4* a, uint2 lo, uint2 hi) {
    asm volatile("red.global.add.noftz.v4.f16x2 [%0], {%1,%2,%3,%4};"
                 :: "l"(a), "r"(lo.x), "r"(lo.y), "r"(hi.x), "r"(hi.y) : "memory");
}

__device__ __forceinline__ float4 f4zero() { return make_float4(0.f, 0.f, 0.f, 0.f); }

__device__ __forceinline__ void f4fma(float4& acc, float s, const float4 w) {
    acc.x = fmaf(s, w.x, acc.x);
    acc.y = fmaf(s, w.y, acc.y);
    acc.z = fmaf(s, w.z, acc.z);
    acc.w = fmaf(s, w.w, acc.w);
}

__device__ __forceinline__ float4 f4relu_add(float4 a, float4 b) {
    return make_float4(fmaxf(a.x + b.x, 0.f), fmaxf(a.y + b.y, 0.f),
                       fmaxf(a.z + b.z, 0.f), fmaxf(a.w + b.w, 0.f));
}

__device__ __forceinline__ uint2 f4_to_h4(float4 v) {
    __half2 lo = __floats2half2_rn(v.x, v.y);
    __half2 hi = __floats2half2_rn(v.z, v.w);
    uint2 r;
    r.x = *reinterpret_cast<unsigned*>(&lo);
    r.y = *reinterpret_cast<unsigned*>(&hi);
    return r;
}

__device__ __forceinline__ float4 h4_to_f4(uint2 u) {
    __half2 lo = *reinterpret_cast<__half2*>(&u.x);
    __half2 hi = *reinterpret_cast<__half2*>(&u.y);
    float2 a = __half22float2(lo);
    float2 b = __half22float2(hi);
    return make_float4(a.x, a.y, b.x, b.y);
}

// fp16 tensor-core mma: D(f32) += A(f16,row) * B(f16,col), m16n8k16
__device__ __forceinline__ void mma_f16(float c[4], unsigned a0, unsigned a1,
                                        unsigned a2, unsigned a3,
                                        unsigned b0, unsigned b1) {
    asm volatile(
        "mma.sync.aligned.m16n8k16.row.col.f32.f16.f16.f32 "
        "{%0,%1,%2,%3}, {%4,%5,%6,%7}, {%8,%9}, {%0,%1,%2,%3};"
        : "+f"(c[0]), "+f"(c[1]), "+f"(c[2]), "+f"(c[3])
        : "r"(a0), "r"(a1), "r"(a2), "r"(a3), "r"(b0), "r"(b1));
}

// ---------------- counts: batch is sorted -> binary search per graph -------
__global__ void count_kernel(const int* __restrict__ batch) {
    int g = blockIdx.x * blockDim.x + threadIdx.x;
    if (g >= NG) return;
    int lo = 0, hi = NN;
    while (lo < hi) { int m = (lo + hi) >> 1; if (batch[m] < g) lo = m + 1; else hi = m; }
    int s = lo;
    lo = 0; hi = NN;
    while (lo < hi) { int m = (lo + hi) >> 1; if (batch[m] < g + 1) lo = m + 1; else hi = m; }
    d_gcnt[g] = fmaxf((float)(lo - s), 1.0f);
}

// ---------------- input linear: h = x @ W_in + b ; zeroes d_agg16; h16 -----
__global__ void __launch_bounds__(256) lin_in_kernel(const float* __restrict__ x,
                                                     const float* __restrict__ W,
                                                     const float* __restrict__ b) {
    __shared__ __align__(16) float4 Ws[INF_ * HV];
    __shared__ __align__(16) float4 bs[HV];
    int t = threadIdx.x;
    for (int j = t; j < INF_ * HV; j += 256) Ws[j] = ((const float4*)W)[j];
    if (t < HV) bs[t] = ((const float4*)b)[t];
    __syncthreads();

    int lane = t & 15, rloc = t >> 4;
    int row = blockIdx.x * 16 + rloc;

    ((uint2*)d_agg16)[row * HV + lane] = make_uint2(0u, 0u);

    if (row < NN) {
        float4 acc = bs[lane];
        const float* xr = x + row * INF_;
        #pragma unroll
        for (int k = 0; k < INF_; k++) {
            float xv = __ldg(xr + k);
            f4fma(acc, xv, Ws[k * HV + lane]);
        }
        ((float4*)d_h)[row * HV + lane] = acc;
        ((uint2*)d_h16)[row * HV + lane] = f4_to_h4(acc);
    }
}

// ---------------- edge kernel: agg16[dst] += relu(h16[src] + ea @ We + be) -
// 8 lanes/edge, each lane owns 8 channels: uint4 gathers (1 LDG.128/lane)
// and 16B v4.f16x2 REDs — half the L2 transactions of the 16-lane version.
__global__ void __launch_bounds__(256) edge_kernel(const int* __restrict__ ei,
                                                   const float* __restrict__ eattr,
                                                   const float* __restrict__ eW,
                                                   const float* __restrict__ eb) {
    __shared__ __align__(16) float4 Ws[EDIM * HV];
    __shared__ __align__(16) float4 bs[HV];
    int t = threadIdx.x;
    if (t < EDIM * HV) Ws[t] = ((const float4*)eW)[t];
    if (t < HV) bs[t] = ((const float4*)eb)[t];
    __syncthreads();

    int lane8 = t & 7;                         // channel group (8 ch = 2 float4)
    int grp   = t >> 3;                        // edge slot 0..31
    int e0    = blockIdx.x * EPB + grp * 4;    // 4 consecutive edges

    int4 s4 = __ldg((const int4*)(ei) + (e0 >> 2));
    int4 t4 = __ldg((const int4*)(ei + NE) + (e0 >> 2));
    int src[4] = {s4.x, s4.y, s4.z, s4.w};
    int dst[4] = {t4.x, t4.y, t4.z, t4.w};

    uint4 hr[4];
    #pragma unroll
    for (int j = 0; j < 4; j++)
        hr[j] = __ldg((const uint4*)d_h16 + src[j] * 8 + lane8);

    float4 a[4];
    #pragma unroll
    for (int j = 0; j < 4; j++) a[j] = __ldg((const float4*)eattr + e0 + j);

    int c0 = lane8 * 2;
    float4 w00 = Ws[0 * HV + c0], w01 = Ws[0 * HV + c0 + 1];
    float4 w10 = Ws[1 * HV + c0], w11 = Ws[1 * HV + c0 + 1];
    float4 w20 = Ws[2 * HV + c0], w21 = Ws[2 * HV + c0 + 1];
    float4 w30 = Ws[3 * HV + c0], w31 = Ws[3 * HV + c0 + 1];
    float4 bv0 = bs[c0], bv1 = bs[c0 + 1];

    #pragma unroll
    for (int j = 0; j < 4; j++) {
        float4 v0 = bv0, v1 = bv1;
        f4fma(v0, a[j].x, w00); f4fma(v1, a[j].x, w01);
        f4fma(v0, a[j].y, w10); f4fma(v1, a[j].y, w11);
        f4fma(v0, a[j].z, w20); f4fma(v1, a[j].z, w21);
        f4fma(v0, a[j].w, w30); f4fma(v1, a[j].w, w31);
        float4 hlo = h4_to_f4(make_uint2(hr[j].x, hr[j].y));
        float4 hhi = h4_to_f4(make_uint2(hr[j].z, hr[j].w));
        float4 m0 = f4relu_add(v0, hlo);
        float4 m1 = f4relu_add(v1, hhi);
        red_addh8((uint4*)d_agg16 + dst[j] * 8 + lane8, f4_to_h4(m0), f4_to_h4(m1));
    }
}

// ---------------- fused node MLP via fp16 mma, 128-row tile ----------------
// Warp w handles rows m0=w*16, ALL 64 cols (8 n-tiles). 391 blocks, 1 wave.
__global__ void __launch_bounds__(256) mlp_fused_kernel(
    const float* __restrict__ W1, const float* __restrict__ b1,
    const float* __restrict__ g1, const float* __restrict__ be1,
    const float* __restrict__ rm1, const float* __restrict__ rv1,
    const float* __restrict__ W2, const float* __restrict__ b2,
    const float* __restrict__ g2, const float* __restrict__ be2,
    const float* __restrict__ rm2, const float* __restrict__ rv2,
    const float* __restrict__ epsp, const int* __restrict__ batch, int do_pn)
{
    __shared__ __align__(16) __half zs_h[MROWS * KP];
    __shared__ __align__(16) __half WT_h[64 * KP];
    __shared__ float bias1[H], bias2[H];

    int t = threadIdx.x;
    int lane = t & 31, w = t >> 5;
    int tig = lane & 3, g = lane >> 2;
    int m0 = w * 16;
    int R0 = blockIdx.x * MROWS;
    float epv = 1.0f + __ldg(epsp);

    if (t < H) {
        float s1 = __ldg(g1 + t) * rsqrtf(__ldg(rv1 + t) + BN_EPS);
        bias1[t] = fmaf(__ldg(b1 + t) - __ldg(rm1 + t), s1, __ldg(be1 + t));
        float s2 = __ldg(g2 + t) * rsqrtf(__ldg(rv2 + t) + BN_EPS);
        bias2[t] = fmaf(__ldg(b2 + t) - __ldg(rm2 + t), s2, __ldg(be2 + t));
    }

    // --- W1 staging: thread owns column n, k-range [16q,16q+16) ------------
    int n = t & 63, q = t >> 6;
    float s1n = __ldg(g1 + n) * rsqrtf(__ldg(rv1 + n) + BN_EPS);
    float wreg[16];
    #pragma unroll
    for (int j = 0; j < 16; j++)
        wreg[j] = __ldg(W1 + (q * 16 + j) * H + n);
    #pragma unroll
    for (int j = 0; j < 8; j++) {
        __half2 p = __floats2half2_rn(wreg[2 * j] * s1n, wreg[2 * j + 1] * s1n);
        *(__half2*)&WT_h[n * KP + q * 16 + 2 * j] = p;
    }

    // --- z staging: z = (1+eps)*h + agg16, rounded to half -----------------
    #pragma unroll
    for (int s = 0; s < 8; s++) {
        int idx = t + 256 * s;                  // 2048 float4 groups
        int k  = idx >> 4;
        int n4 = (idx & 15) * 4;
        float4 hv = __ldg((const float4*)d_h + R0 * HV + idx);
        float4 av = h4_to_f4(__ldg((const uint2*)d_agg16 + R0 * HV + idx));
        float4 z = make_float4(fmaf(epv, hv.x, av.x), fmaf(epv, hv.y, av.y),
                               fmaf(epv, hv.z, av.z), fmaf(epv, hv.w, av.w));
        *(uint2*)&zs_h[k * KP + n4] = f4_to_h4(z);
        if (do_pn) ((uint2*)d_agg16)[R0 * HV + idx] = make_uint2(0u, 0u);
    }
    __syncthreads();

    // --- GEMM1: 16 rows x 64 cols per warp ---------------------------------
    float c[8][4];
    #pragma unroll
    for (int nt = 0; nt < 8; nt++)
        c[nt][0] = c[nt][1] = c[nt][2] = c[nt][3] = 0.f;
    #pragma unroll
    for (int kk = 0; kk < 4; kk++) {
        int k0 = kk * 16;
        unsigned a0 = *(const unsigned*)&zs_h[(m0 + g) * KP + k0 + 2 * tig];
        unsigned a1 = *(const unsigned*)&zs_h[(m0 + g + 8) * KP + k0 + 2 * tig];
        unsigned a2 = *(const unsigned*)&zs_h[(m0 + g) * KP + k0 + 2 * tig + 8];
        unsigned a3 = *(const unsigned*)&zs_h[(m0 + g + 8) * KP + k0 + 2 * tig + 8];
        #pragma unroll
        for (int nt = 0; nt < 8; nt++) {
            const __half* bp = &WT_h[(nt * 8 + g) * KP + k0 + 2 * tig];
            unsigned b0 = *(const unsigned*)bp;
            unsigned b1 = *(const unsigned*)(bp + 8);
            mma_f16(c[nt], a0, a1, a2, a3, b0, b1);
        }
    }

    // --- W2 prefetch (overlaps barrier wait) -------------------------------
    float s2n = __ldg(g2 + n) * rsqrtf(__ldg(rv2 + n) + BN_EPS);
    #pragma unroll
    for (int j = 0; j < 16; j++)
        wreg[j] = __ldg(W2 + (q * 16 + j) * H + n);

    __syncthreads();

    // --- stage t = relu(c + bias1) -> zs_h ; scaled W2 -> WT_h -------------
    #pragma unroll
    for (int nt = 0; nt < 8; nt++) {
        int col = nt * 8 + 2 * tig;
        float bA0 = bias1[col], bA1 = bias1[col + 1];
        float v0 = fmaxf(c[nt][0] + bA0, 0.f), v1 = fmaxf(c[nt][1] + bA1, 0.f);
        float v2 = fmaxf(c[nt][2] + bA0, 0.f), v3 = fmaxf(c[nt][3] + bA1, 0.f);
        *(__half2*)&zs_h[(m0 + g) * KP + col]     = __floats2half2_rn(v0, v1);
        *(__half2*)&zs_h[(m0 + g + 8) * KP + col] = __floats2half2_rn(v2, v3);
    }
    #pragma unroll
    for (int j = 0; j < 8; j++) {
        __half2 p = __floats2half2_rn(wreg[2 * j] * s2n, wreg[2 * j + 1] * s2n);
        *(__half2*)&WT_h[n * KP + q * 16 + 2 * j] = p;
    }
    __syncthreads();

    // --- GEMM2 --------------------------------------------------------------
    #pragma unroll
    for (int nt = 0; nt < 8; nt++)
        c[nt][0] = c[nt][1] = c[nt][2] = c[nt][3] = 0.f;
    #pragma unroll
    for (int kk = 0; kk < 4; kk++) {
        int k0 = kk * 16;
        unsigned a0 = *(const unsigned*)&zs_h[(m0 + g) * KP + k0 + 2 * tig];
        unsigned a1 = *(const unsigned*)&zs_h[(m0 + g + 8) * KP + k0 + 2 * tig];
        unsigned a2 = *(const unsigned*)&zs_h[(m0 + g) * KP + k0 + 2 * tig + 8];
        unsigned a3 = *(const unsigned*)&zs_h[(m0 + g + 8) * KP + k0 + 2 * tig + 8];
        #pragma unroll
        for (int nt = 0; nt < 8; nt++) {
            const __half* bp = &WT_h[(nt * 8 + g) * KP + k0 + 2 * tig];
            unsigned b0 = *(const unsigned*)bp;
            unsigned b1 = *(const unsigned*)(bp + 8);
            mma_f16(c[nt], a0, a1, a2, a3, b0, b1);
        }
    }

    // --- epilogue: BN2+ReLU, store h, PN stats / pool ----------------------
    int rowA = R0 + m0 + g;
    int rowB = rowA + 8;
    bool okA = rowA < NN, okB = rowB < NN;
    int ggA = okA ? __ldg(batch + rowA) : 0;
    int ggB = okB ? __ldg(batch + rowB) : 0;
    float sqA = 0.f, sqB = 0.f;

    #pragma unroll
    for (int nt = 0; nt < 8; nt++) {
        int col = nt * 8 + 2 * tig;
        float bA0 = bias2[col], bA1 = bias2[col + 1];
        float v0 = fmaxf(c[nt][0] + bA0, 0.f), v1 = fmaxf(c[nt][1] + bA1, 0.f);
        float v2 = fmaxf(c[nt][2] + bA0, 0.f), v3 = fmaxf(c[nt][3] + bA1, 0.f);
        if (okA) *(float2*)&d_h[rowA * H + col] = make_float2(v0, v1);
        if (okB) *(float2*)&d_h[rowB * H + col] = make_float2(v2, v3);
        if (do_pn) {
            if (okA) red_add2((float2*)&d_gsum[ggA * H + col], v0, v1);
            if (okB) red_add2((float2*)&d_gsum[ggB * H + col], v2, v3);
            sqA = fmaf(v0, v0, fmaf(v1, v1, sqA));
            sqB = fmaf(v2, v2, fmaf(v3, v3, sqB));
        } else {
            if (okA) red_add2((float2*)&d_pool[ggA * H + col], v0, v1);
            if (okB) red_add2((float2*)&d_pool[ggB * H + col], v2, v3);
        }
    }
    if (do_pn) {
        sqA += __shfl_xor_sync(0xffffffffu, sqA, 1);
        sqA += __shfl_xor_sync(0xffffffffu, sqA, 2);
        sqB += __shfl_xor_sync(0xffffffffu, sqB, 1);
        sqB += __shfl_xor_sync(0xffffffffu, sqB, 2);
        if (tig == 0) {
            if (okA) atomicAdd(&d_gss[ggA], sqA);
            if (okB) atomicAdd(&d_gss[ggB], sqB);
        }
    }
}

// ---------------- PairNorm per-graph mean & inverse denom; self-re-zeros ---
__global__ void meaninv_kernel() {
    int g = blockIdx.x, c = threadIdx.x;     // 64 threads
    float cnt = d_gcnt[g];
    float s = d_gsum[g * H + c];
    d_gsum[g * H + c] = 0.f;
    float mean = s / cnt;
    d_mean[g * H + c] = mean;
    float part = mean * s;
    #pragma unroll
    for (int o = 16; o; o >>= 1) part += __shfl_down_sync(0xffffffffu, part, o);
    __shared__ float red[2];
    if ((c & 31) == 0) red[c >> 5] = part;
    __syncthreads();
    if (c == 0) {
        float ss = d_gss[g];
        d_gss[g] = 0.f;
        float var = (ss - (red[0] + red[1])) / cnt;
        d_invd[g] = rsqrtf(PN_EPS + var);
    }
}

// ---------------- PairNorm apply (also writes fp16 shadow) -----------------
__global__ void __launch_bounds__(256) norm_kernel(const int* __restrict__ batch) {
    int idx = blockIdx.x * 256 + threadIdx.x;    // exactly NN*HV
    int row = idx >> 4, ln = idx & 15;
    int g = __ldg(batch + row);
    float4 hv = ((const float4*)d_h)[idx];
    float4 m = ((const float4*)d_mean)[g * HV + ln];
    float id = d_invd[g];
    hv.x = (hv.x - m.x) * id;
    hv.y = (hv.y - m.y) * id;
    hv.z = (hv.z - m.z) * id;
    hv.w = (hv.w - m.w) * id;
    ((float4*)d_h)[idx] = hv;
    ((uint2*)d_h16)[idx] = f4_to_h4(hv);
}

// ---------------- classifier; self-re-zeros pool ---------------------------
__global__ void cls_kernel(const float* __restrict__ W, const float* __restrict__ b,
                           float* __restrict__ out) {
    int g = blockIdx.x, c = threadIdx.x;     // 64 threads
    float p = d_pool[g * H + c];
    d_pool[g * H + c] = 0.f;
    float a = p * W[c * NOUT + 0];
    float bb = p * W[c * NOUT + 1];
    #pragma unroll
    for (int o = 16; o; o >>= 1) {
        a  += __shfl_down_sync(0xffffffffu, a, o);
        bb += __shfl_down_sync(0xffffffffu, bb, o);
    }
    __shared__ float sa[2], sb[2];
    if ((c & 31) == 0) { sa[c >> 5] = a; sb[c >> 5] = bb; }
    __syncthreads();
    if (c == 0) {
        out[g * NOUT + 0] = sa[0] + sa[1] + b[0];
        out[g * NOUT + 1] = sb[0] + sb[1] + b[1];
    }
}

// ---------------------------------------------------------------------------
extern "C" void kernel_launch(void* const* d_in, const int* in_sizes, int n_in,
                              void* d_out, int out_size) {
    const float* x        = (const float*)d_in[0];
    const int*   ei       = (const int*)  d_in[1];
    const float* eattr    = (const float*)d_in[2];
    const int*   batch    = (const int*)  d_in[3];
    const float* lin_W    = (const float*)d_in[4];
    const float* lin_b    = (const float*)d_in[5];
    const float* edge_W   = (const float*)d_in[6];
    const float* edge_b   = (const float*)d_in[7];
    const float* mlp_W1   = (const float*)d_in[8];
    const float* mlp_b1   = (const float*)d_in[9];
    const float* mbn_g    = (const float*)d_in[10];
    const float* mbn_b    = (const float*)d_in[11];
    const float* mbn_rm   = (const float*)d_in[12];
    const float* mbn_rv   = (const float*)d_in[13];
    const float* mlp_W2   = (const float*)d_in[14];
    const float* mlp_b2   = (const float*)d_in[15];
    const float* eps      = (const float*)d_in[16];
    const float* bn_g     = (const float*)d_in[17];
    const float* bn_b     = (const float*)d_in[18];
    const float* bn_rm    = (const float*)d_in[19];
    const float* bn_rv    = (const float*)d_in[20];
    const float* cls_W    = (const float*)d_in[21];
    const float* cls_b    = (const float*)d_in[22];
    float* out = (float*)d_out;

    count_kernel<<<2, 256>>>(batch);
    lin_in_kernel<<<NPAD / 16, 256>>>(x, lin_W, lin_b);

    for (int i = 0; i < NL; i++) {
        edge_kernel<<<NE / EPB, 256>>>(ei, eattr, edge_W + i * EDIM * H, edge_b + i * H);
        int do_pn = (i < NL - 1) ? 1 : 0;
        mlp_fused_kernel<<<NPAD / MROWS, 256>>>(
            mlp_W1 + i * H * H, mlp_b1 + i * H,
            mbn_g + i * H, mbn_b + i * H, mbn_rm + i * H, mbn_rv + i * H,
            mlp_W2 + i * H * H, mlp_b2 + i * H,
            bn_g + i * H, bn_b + i * H, bn_rm + i * H, bn_rv + i * H,
            eps + i, batch, do_pn);
        if (do_pn) {
            meaninv_kernel<<<NG, H>>>();
            norm_kernel<<<(NN * HV) / 256, 256>>>(batch);
        }
    }

    cls_kernel<<<NG, H>>>(cls_W, cls_b, out);
}